// round 3
// baseline (speedup 1.0000x reference)
#include <cuda_runtime.h>
#include <math.h>

#define T_LEN      220500
#define NCH        64
#define CHUNK      84
#define NCHUNK_CH  2625                // 220500 / 84
#define NCHUNK_TOT 168000              // 64 * 2625
#define TOTAL_F4   3528000             // 14,112,000 / 4
#define BT         128
#define NW         (BT / 32)
#define TILE       (BT * CHUNK)        // 10752 floats = 43008 B
#define F4PB       (TILE / 4)          // 2688
#define NBLK       ((NCHUNK_TOT + BT - 1) / BT)   // 1313

__device__ float4 g_incl[NBLK];        // inclusive state after block: (sL1,sL2,sH1,sH2)
__device__ int    g_flag[NBLK];

struct Map { float a, b, c, d, p, q; };   // s -> [a b; c d] s + (p,q)

__device__ __forceinline__ Map mapIdent() { Map m = {1.f,0.f,0.f,1.f,0.f,0.f}; return m; }
// hi applied AFTER lo
__device__ __forceinline__ Map mapCompose(const Map& hi, const Map& lo) {
    Map r;
    r.a = fmaf(hi.a, lo.a, hi.b * lo.c);
    r.b = fmaf(hi.a, lo.b, hi.b * lo.d);
    r.c = fmaf(hi.c, lo.a, hi.d * lo.c);
    r.d = fmaf(hi.c, lo.b, hi.d * lo.d);
    r.p = fmaf(hi.a, lo.p, fmaf(hi.b, lo.q, hi.p));
    r.q = fmaf(hi.c, lo.p, fmaf(hi.d, lo.q, hi.q));
    return r;
}
__device__ __forceinline__ float2 mapApply(const Map& m, float vx, float vy) {
    return make_float2(fmaf(m.a, vx, fmaf(m.b, vy, m.p)),
                       fmaf(m.c, vx, fmaf(m.d, vy, m.q)));
}
__device__ __forceinline__ Map mapShflUp(const Map& m, int d) {
    Map r;
    r.a = __shfl_up_sync(0xffffffffu, m.a, d);
    r.b = __shfl_up_sync(0xffffffffu, m.b, d);
    r.c = __shfl_up_sync(0xffffffffu, m.c, d);
    r.d = __shfl_up_sync(0xffffffffu, m.d, d);
    r.p = __shfl_up_sync(0xffffffffu, m.p, d);
    r.q = __shfl_up_sync(0xffffffffu, m.q, d);
    return r;
}

__global__ void init_kernel() {
    int i = blockIdx.x * blockDim.x + threadIdx.x;
    if (i < NBLK) g_flag[i] = 0;
}

#define BSTEP(xk, ok) {                                          \
    float ffL = fmaf(bL0, (xk), fmaf(bL1, xm1, bL2 * xm2));      \
    float ffH = fmaf(bH0, (xk), fmaf(bH1, xm1, bH2 * xm2));      \
    float yL  = fmaf(nL1, l1, fmaf(nL2, l2, ffL));               \
    float yH  = fmaf(nH1, h1, fmaf(nH2, h2, ffH));               \
    (ok) = yL - yH;                                              \
    l2 = l1; l1 = yL; h2 = h1; h1 = yH;                          \
    xm2 = xm1; xm1 = (xk); }

__global__ __launch_bounds__(BT, 5)
void fused_kernel(const float* __restrict__ x, float* __restrict__ out,
                  const int* __restrict__ sr_p,
                  const float* __restrict__ cl_p,
                  const float* __restrict__ ch_p) {
    __shared__ float  sbuf[TILE];
    __shared__ float  scoef[10];
    __shared__ float4 stab[CHUNK];       // (uL,vL,uH,vH) per sample
    __shared__ Map    sWarpL[NW], sWarpH[NW], sExclL[NW], sExclH[NW];
    __shared__ Map    sAggL, sAggH;
    __shared__ float4 sVin;

    int t   = threadIdx.x;
    int bid = blockIdx.x;

    // ---- stage tile coalesced ----
    size_t base4 = (size_t)bid * F4PB;
    const float4* xg4 = (const float4*)x;
    float4* s4 = (float4*)sbuf;
#pragma unroll
    for (int i = 0; i < F4PB / BT; i++) {
        size_t idx = base4 + t + (size_t)i * BT;
        if (idx < TOTAL_F4) s4[t + i * BT] = xg4[idx];
    }

    // ---- thread 0: coefficients (float, matches f32 reference closely) ----
    if (t == 0) {
        int iv = *sr_p;
        float sr = (iv > 0 && iv < 100000000) ? (float)iv : __int_as_float(iv);
        const float Q = 0.707f;
        {
            float w0 = 2.0f * 3.14159265358979323846f * (*cl_p) / sr;
            float c  = cosf(w0);
            float al = sinf(w0) / (2.0f * Q);
            float a0 = 1.0f + al;
            scoef[0] = ((1.0f - c) * 0.5f) / a0;
            scoef[1] = (1.0f - c) / a0;
            scoef[2] = scoef[0];
            scoef[3] = (-2.0f * c) / a0;
            scoef[4] = (1.0f - al) / a0;
        }
        {
            float w0 = 2.0f * 3.14159265358979323846f * (*ch_p) / sr;
            float c  = cosf(w0);
            float al = sinf(w0) / (2.0f * Q);
            float a0 = 1.0f + al;
            scoef[5] = ((1.0f + c) * 0.5f) / a0;
            scoef[6] = -(1.0f + c) / a0;
            scoef[7] = scoef[5];
            scoef[8] = (-2.0f * c) / a0;
            scoef[9] = (1.0f - al) / a0;
        }
    }
    __syncthreads();

    float bL0 = scoef[0], bL1 = scoef[1], bL2 = scoef[2];
    float nL1 = -scoef[3], nL2 = -scoef[4];
    float bH0 = scoef[5], bH1 = scoef[6], bH2 = scoef[7];
    float nH1 = -scoef[8], nH2 = -scoef[9];

    int  g       = bid * BT + t;
    bool valid   = g < NCHUNK_TOT;
    bool resetCk = valid && (g % NCHUNK_CH) == 0;   // chunk is channel start

    // FIR history (read BEFORE in-place overwrite)
    float xm1 = 0.f, xm2 = 0.f;
    if (valid && !resetCk) {
        if (t == 0) {
            size_t s0 = (size_t)g * CHUNK;
            xm1 = x[s0 - 1];
            xm2 = x[s0 - 2];
        } else {
            xm1 = sbuf[t * CHUNK - 1];
            xm2 = sbuf[t * CHUNK - 2];
        }
    }
    __syncthreads();

    // ---- zero-init recurrence, y0 in place ----
    float l1 = 0.f, l2 = 0.f, h1 = 0.f, h2 = 0.f;
    if (valid) {
        float* cb = sbuf + t * CHUNK;
#pragma unroll 1
        for (int k = 0; k < CHUNK; k += 4) {
            float4 xv = *reinterpret_cast<const float4*>(cb + k);
            float4 ov;
            BSTEP(xv.x, ov.x);
            BSTEP(xv.y, ov.y);
            BSTEP(xv.z, ov.z);
            BSTEP(xv.w, ov.w);
            *reinterpret_cast<float4*>(cb + k) = ov;
        }
    }

    // ---- homogeneous basis table (threads 0-3, one basis each) ----
    if (t < 4) {
        float na1 = (t < 2) ? nL1 : nH1;
        float na2 = (t < 2) ? nL2 : nH2;
        float y1 = (t & 1) ? 0.f : 1.f;    // basis u: init (1,0); v: (0,1)
        float y2 = (t & 1) ? 1.f : 0.f;
        float* sf = (float*)stab;
#pragma unroll 1
        for (int n = 0; n < CHUNK; n++) {
            float y = fmaf(na1, y1, na2 * y2);
            sf[n * 4 + t] = y;
            y2 = y1; y1 = y;
        }
    }
    int hasReset = __syncthreads_or(resetCk ? 1 : 0);

    float4 t83 = stab[CHUNK - 1];
    float4 t82 = stab[CHUNK - 2];
    Map A84L = { t83.x, t83.y, t82.x, t82.y, 0.f, 0.f };
    Map A84H = { t83.z, t83.w, t82.z, t82.w, 0.f, 0.f };

    // ---- per-chunk affine maps ----
    Map mL, mH;
    if (!valid) { mL = mapIdent(); mH = mapIdent(); }
    else if (resetCk) {
        mL.a = mL.b = mL.c = mL.d = 0.f; mL.p = l1; mL.q = l2;
        mH.a = mH.b = mH.c = mH.d = 0.f; mH.p = h1; mH.q = h2;
    } else {
        mL = A84L; mL.p = l1; mL.q = l2;
        mH = A84H; mH.p = h1; mH.q = h2;
    }

    // ---- warp inclusive scan ----
    int lane = t & 31, w = t >> 5;
#pragma unroll
    for (int off = 1; off < 32; off <<= 1) {
        Map pL = mapShflUp(mL, off);
        Map pH = mapShflUp(mH, off);
        if (lane >= off) { mL = mapCompose(mL, pL); mH = mapCompose(mH, pH); }
    }
    if (lane == 31) { sWarpL[w] = mL; sWarpH[w] = mH; }
    __syncthreads();
    if (t == 0) {
        Map eL = mapIdent(), eH = mapIdent();
#pragma unroll
        for (int i = 0; i < NW; i++) {
            sExclL[i] = eL; sExclH[i] = eH;
            eL = mapCompose(sWarpL[i], eL);
            eH = mapCompose(sWarpH[i], eH);
        }
        sAggL = eL; sAggH = eH;     // full block aggregate
    }
    __syncthreads();

    // thread-exclusive within warp
    Map exL = mapShflUp(mL, 1);
    Map exH = mapShflUp(mH, 1);
    if (lane == 0) { exL = mapIdent(); exH = mapIdent(); }
    exL = mapCompose(exL, sExclL[w]);
    exH = mapCompose(exH, sExclH[w]);

    // ---- inter-block deterministic look-back (thread 0) ----
    if (t == 0) {
        bool needVin = ((bid * BT) % NCHUNK_CH) != 0;   // block not channel-aligned
        float4 vin = make_float4(0.f, 0.f, 0.f, 0.f);
        if (hasReset) {
            // inclusive independent of incoming state: publish first
            float4 incl = make_float4(sAggL.p, sAggL.q, sAggH.p, sAggH.q);
            __stcg(&g_incl[bid], incl);
            __threadfence();
            atomicExch(&g_flag[bid], 1);
            if (needVin) {
                while (atomicAdd(&g_flag[bid - 1], 0) == 0) __nanosleep(64);
                __threadfence();
                vin = __ldcg(&g_incl[bid - 1]);
            }
        } else {
            // needVin is necessarily true here (channel-aligned => reset)
            while (atomicAdd(&g_flag[bid - 1], 0) == 0) __nanosleep(64);
            __threadfence();
            vin = __ldcg(&g_incl[bid - 1]);
            float2 oL = mapApply(sAggL, vin.x, vin.y);
            float2 oH = mapApply(sAggH, vin.z, vin.w);
            __stcg(&g_incl[bid], make_float4(oL.x, oL.y, oH.x, oH.y));
            __threadfence();
            atomicExch(&g_flag[bid], 1);
        }
        sVin = vin;
    }
    __syncthreads();
    float4 vin = sVin;

    // ---- correction: y = y0 + u*s1 + v*s2 (chain-free) ----
    if (valid) {
        float2 sL = resetCk ? make_float2(0.f, 0.f) : mapApply(exL, vin.x, vin.y);
        float2 sH = resetCk ? make_float2(0.f, 0.f) : mapApply(exH, vin.z, vin.w);
        float sL1 = sL.x, sL2 = sL.y, nsH1 = -sH.x, nsH2 = -sH.y;
        float* cb = sbuf + t * CHUNK;
#pragma unroll 1
        for (int k = 0; k < CHUNK; k += 4) {
            float4 yv = *reinterpret_cast<const float4*>(cb + k);
            float4 t0 = stab[k], t1 = stab[k + 1], t2 = stab[k + 2], t3 = stab[k + 3];
            yv.x += fmaf(t0.x, sL1, fmaf(t0.y, sL2, fmaf(t0.z, nsH1, t0.w * nsH2)));
            yv.y += fmaf(t1.x, sL1, fmaf(t1.y, sL2, fmaf(t1.z, nsH1, t1.w * nsH2)));
            yv.z += fmaf(t2.x, sL1, fmaf(t2.y, sL2, fmaf(t2.z, nsH1, t2.w * nsH2)));
            yv.w += fmaf(t3.x, sL1, fmaf(t3.y, sL2, fmaf(t3.z, nsH1, t3.w * nsH2)));
            *reinterpret_cast<float4*>(cb + k) = yv;
        }
    }
    __syncthreads();

    // ---- coalesced store ----
    float4* og4 = (float4*)out;
#pragma unroll
    for (int i = 0; i < F4PB / BT; i++) {
        size_t idx = base4 + t + (size_t)i * BT;
        if (idx < TOTAL_F4) og4[idx] = s4[t + i * BT];
    }
}

extern "C" void kernel_launch(void* const* d_in, const int* in_sizes, int n_in,
                              void* d_out, int out_size) {
    const float* audio = (const float*)d_in[0];
    const int*   sr    = (const int*)d_in[1];
    const float* cl    = (const float*)d_in[2];
    const float* ch    = (const float*)d_in[3];
    float* out = (float*)d_out;

    init_kernel<<<(NBLK + 255) / 256, 256>>>();
    fused_kernel<<<NBLK, BT>>>(audio, out, sr, cl, ch);
}

// round 4
// speedup vs baseline: 1.6127x; 1.6127x over previous
#include <cuda_runtime.h>
#include <math.h>

#define T_LEN      220500
#define NCH        64
#define CHUNK      84
#define NCHUNK_CH  2625                // 220500 / 84
#define NCHUNK_TOT 168000              // 64 * 2625
#define TOTAL_F4   3528000             // 14,112,000 / 4
#define BT         128
#define NW         (BT / 32)
#define TILE       (BT * CHUNK)        // 10752 floats = 43008 B
#define F4PB       (TILE / 4)          // 2688
#define NBLK       ((NCHUNK_TOT + BT - 1) / BT)   // 1313
#define WIN        24                  // reset blocks occur every 20-21 blocks

// published per-block aggregate: [0]=(La,Lb,Lc,Ld) [1]=(Lp,Lq,Hp,Hq) [2]=(Ha,Hb,Hc,Hd)
__device__ float4 g_agg[NBLK][3];
__device__ int    g_flag[NBLK];

struct Map { float a, b, c, d, p, q; };   // s -> [a b; c d] s + (p,q)

__device__ __forceinline__ Map mapIdent() { Map m = {1.f,0.f,0.f,1.f,0.f,0.f}; return m; }
// hi applied AFTER lo
__device__ __forceinline__ Map mapCompose(const Map& hi, const Map& lo) {
    Map r;
    r.a = fmaf(hi.a, lo.a, hi.b * lo.c);
    r.b = fmaf(hi.a, lo.b, hi.b * lo.d);
    r.c = fmaf(hi.c, lo.a, hi.d * lo.c);
    r.d = fmaf(hi.c, lo.b, hi.d * lo.d);
    r.p = fmaf(hi.a, lo.p, fmaf(hi.b, lo.q, hi.p));
    r.q = fmaf(hi.c, lo.p, fmaf(hi.d, lo.q, hi.q));
    return r;
}
__device__ __forceinline__ float2 mapApply(const Map& m, float vx, float vy) {
    return make_float2(fmaf(m.a, vx, fmaf(m.b, vy, m.p)),
                       fmaf(m.c, vx, fmaf(m.d, vy, m.q)));
}
__device__ __forceinline__ Map mapShflUp(const Map& m, int d) {
    Map r;
    r.a = __shfl_up_sync(0xffffffffu, m.a, d);
    r.b = __shfl_up_sync(0xffffffffu, m.b, d);
    r.c = __shfl_up_sync(0xffffffffu, m.c, d);
    r.d = __shfl_up_sync(0xffffffffu, m.d, d);
    r.p = __shfl_up_sync(0xffffffffu, m.p, d);
    r.q = __shfl_up_sync(0xffffffffu, m.q, d);
    return r;
}

__global__ void init_kernel() {
    int i = blockIdx.x * blockDim.x + threadIdx.x;
    if (i < NBLK) g_flag[i] = 0;
}

#define BSTEP(xk, ok) {                                          \
    float ffL = fmaf(bL0, (xk), fmaf(bL1, xm1, bL2 * xm2));      \
    float ffH = fmaf(bH0, (xk), fmaf(bH1, xm1, bH2 * xm2));      \
    float yL  = fmaf(nL1, l1, fmaf(nL2, l2, ffL));               \
    float yH  = fmaf(nH1, h1, fmaf(nH2, h2, ffH));               \
    (ok) = yL - yH;                                              \
    l2 = l1; l1 = yL; h2 = h1; h1 = yH;                          \
    xm2 = xm1; xm1 = (xk); }

__global__ __launch_bounds__(BT)
void fused_kernel(const float* __restrict__ x, float* __restrict__ out,
                  const int* __restrict__ sr_p,
                  const float* __restrict__ cl_p,
                  const float* __restrict__ ch_p) {
    __shared__ float  sbuf[TILE];
    __shared__ float  scoef[10];
    __shared__ float4 stab[CHUNK];       // (uL,vL,uH,vH) per sample
    __shared__ Map    sWarpL[NW], sWarpH[NW], sExclL[NW], sExclH[NW];
    __shared__ Map    sAggL, sAggH;
    __shared__ float4 sPred[WIN][3];
    __shared__ float4 sVin;

    int t   = threadIdx.x;
    int bid = blockIdx.x;

    // ---- stage tile coalesced ----
    size_t base4 = (size_t)bid * F4PB;
    const float4* xg4 = (const float4*)x;
    float4* s4 = (float4*)sbuf;
#pragma unroll
    for (int i = 0; i < F4PB / BT; i++) {
        size_t idx = base4 + t + (size_t)i * BT;
        if (idx < TOTAL_F4) s4[t + i * BT] = xg4[idx];
    }

    // ---- thread 0: coefficients ----
    if (t == 0) {
        int iv = *sr_p;
        float sr = (iv > 0 && iv < 100000000) ? (float)iv : __int_as_float(iv);
        const float Q = 0.707f;
        {
            float w0 = 2.0f * 3.14159265358979323846f * (*cl_p) / sr;
            float c  = cosf(w0);
            float al = sinf(w0) / (2.0f * Q);
            float a0 = 1.0f + al;
            scoef[0] = ((1.0f - c) * 0.5f) / a0;
            scoef[1] = (1.0f - c) / a0;
            scoef[2] = scoef[0];
            scoef[3] = (-2.0f * c) / a0;
            scoef[4] = (1.0f - al) / a0;
        }
        {
            float w0 = 2.0f * 3.14159265358979323846f * (*ch_p) / sr;
            float c  = cosf(w0);
            float al = sinf(w0) / (2.0f * Q);
            float a0 = 1.0f + al;
            scoef[5] = ((1.0f + c) * 0.5f) / a0;
            scoef[6] = -(1.0f + c) / a0;
            scoef[7] = scoef[5];
            scoef[8] = (-2.0f * c) / a0;
            scoef[9] = (1.0f - al) / a0;
        }
    }
    __syncthreads();

    float bL0 = scoef[0], bL1 = scoef[1], bL2 = scoef[2];
    float nL1 = -scoef[3], nL2 = -scoef[4];
    float bH0 = scoef[5], bH1 = scoef[6], bH2 = scoef[7];
    float nH1 = -scoef[8], nH2 = -scoef[9];

    int  g       = bid * BT + t;
    bool valid   = g < NCHUNK_TOT;
    bool resetCk = valid && (g % NCHUNK_CH) == 0;   // chunk is channel start

    // FIR history (read BEFORE in-place overwrite)
    float xm1 = 0.f, xm2 = 0.f;
    if (valid && !resetCk) {
        if (t == 0) {
            size_t s0 = (size_t)g * CHUNK;
            xm1 = x[s0 - 1];
            xm2 = x[s0 - 2];
        } else {
            xm1 = sbuf[t * CHUNK - 1];
            xm2 = sbuf[t * CHUNK - 2];
        }
    }
    __syncthreads();

    // ---- zero-init recurrence, y0 in place ----
    float l1 = 0.f, l2 = 0.f, h1 = 0.f, h2 = 0.f;
    if (valid) {
        float* cb = sbuf + t * CHUNK;
#pragma unroll 1
        for (int k = 0; k < CHUNK; k += 4) {
            float4 xv = *reinterpret_cast<const float4*>(cb + k);
            float4 ov;
            BSTEP(xv.x, ov.x);
            BSTEP(xv.y, ov.y);
            BSTEP(xv.z, ov.z);
            BSTEP(xv.w, ov.w);
            *reinterpret_cast<float4*>(cb + k) = ov;
        }
    }

    // ---- homogeneous basis table (threads 0-3, one basis each) ----
    if (t < 4) {
        float na1 = (t < 2) ? nL1 : nH1;
        float na2 = (t < 2) ? nL2 : nH2;
        float y1 = (t & 1) ? 0.f : 1.f;
        float y2 = (t & 1) ? 1.f : 0.f;
        float* sf = (float*)stab;
#pragma unroll 1
        for (int n = 0; n < CHUNK; n++) {
            float y = fmaf(na1, y1, na2 * y2);
            sf[n * 4 + t] = y;
            y2 = y1; y1 = y;
        }
    }
    __syncthreads();

    float4 t83 = stab[CHUNK - 1];
    float4 t82 = stab[CHUNK - 2];
    Map A84L = { t83.x, t83.y, t82.x, t82.y, 0.f, 0.f };
    Map A84H = { t83.z, t83.w, t82.z, t82.w, 0.f, 0.f };

    // ---- per-chunk affine maps ----
    Map mL, mH;
    if (!valid) { mL = mapIdent(); mH = mapIdent(); }
    else if (resetCk) {
        mL.a = mL.b = mL.c = mL.d = 0.f; mL.p = l1; mL.q = l2;
        mH.a = mH.b = mH.c = mH.d = 0.f; mH.p = h1; mH.q = h2;
    } else {
        mL = A84L; mL.p = l1; mL.q = l2;
        mH = A84H; mH.p = h1; mH.q = h2;
    }

    // ---- warp inclusive scan ----
    int lane = t & 31, w = t >> 5;
#pragma unroll
    for (int off = 1; off < 32; off <<= 1) {
        Map pL = mapShflUp(mL, off);
        Map pH = mapShflUp(mH, off);
        if (lane >= off) { mL = mapCompose(mL, pL); mH = mapCompose(mH, pH); }
    }
    if (lane == 31) { sWarpL[w] = mL; sWarpH[w] = mH; }
    __syncthreads();

    // ---- block aggregate + IMMEDIATE publish (no waiting before publish!) ----
    if (t == 0) {
        Map eL = mapIdent(), eH = mapIdent();
#pragma unroll
        for (int i = 0; i < NW; i++) {
            sExclL[i] = eL; sExclH[i] = eH;
            eL = mapCompose(sWarpL[i], eL);
            eH = mapCompose(sWarpH[i], eH);
        }
        sAggL = eL; sAggH = eH;
        __stcg(&g_agg[bid][0], make_float4(eL.a, eL.b, eL.c, eL.d));
        __stcg(&g_agg[bid][1], make_float4(eL.p, eL.q, eH.p, eH.q));
        __stcg(&g_agg[bid][2], make_float4(eH.a, eH.b, eH.c, eH.d));
        __threadfence();
        atomicExch(&g_flag[bid], 1);
    }

    // ---- parallel-window look-back (warp 0) ----
    // Any block containing a reset chunk has an exactly-zero aggregate matrix
    // (composition through a zero matrix). Reset blocks occur every <=21
    // blocks, so the nearest zero-matrix predecessor is within WIN=24.
    if (w == 0) {
        int pred = bid - 1 - t;
        if (t < WIN && pred >= 0) {
            while (atomicAdd(&g_flag[pred], 0) == 0) __nanosleep(32);
            __threadfence();
            sPred[t][0] = __ldcg(&g_agg[pred][0]);
            sPred[t][1] = __ldcg(&g_agg[pred][1]);
            sPred[t][2] = __ldcg(&g_agg[pred][2]);
        }
        __syncwarp();
        if (t == 0) {
            float4 vin = make_float4(0.f, 0.f, 0.f, 0.f);
            if (bid > 0) {
                int nAvail = (bid < WIN) ? bid : WIN;
                // find nearest predecessor whose matrices are exactly zero
                int term = nAvail - 1;
                for (int i = 0; i < nAvail; i++) {
                    float4 fL = sPred[i][0];
                    float4 fH = sPred[i][2];
                    if (fL.x == 0.f && fL.y == 0.f && fL.z == 0.f && fL.w == 0.f &&
                        fH.x == 0.f && fH.y == 0.f && fH.z == 0.f && fH.w == 0.f) {
                        term = i;
                        break;
                    }
                }
                float4 off0 = sPred[term][1];
                float sLx = off0.x, sLy = off0.y, sHx = off0.z, sHy = off0.w;
                for (int i = term - 1; i >= 0; i--) {
                    float4 fL = sPred[i][0];
                    float4 fH = sPred[i][2];
                    float4 fo = sPred[i][1];
                    float nLx = fmaf(fL.x, sLx, fmaf(fL.y, sLy, fo.x));
                    float nLy = fmaf(fL.z, sLx, fmaf(fL.w, sLy, fo.y));
                    float nHx = fmaf(fH.x, sHx, fmaf(fH.y, sHy, fo.z));
                    float nHy = fmaf(fH.z, sHx, fmaf(fH.w, sHy, fo.w));
                    sLx = nLx; sLy = nLy; sHx = nHx; sHy = nHy;
                }
                vin = make_float4(sLx, sLy, sHx, sHy);
            }
            sVin = vin;
        }
    }
    __syncthreads();
    float4 vin = sVin;

    // thread-exclusive map within block
    Map exL = mapShflUp(mL, 1);
    Map exH = mapShflUp(mH, 1);
    if (lane == 0) { exL = mapIdent(); exH = mapIdent(); }
    exL = mapCompose(exL, sExclL[w]);
    exH = mapCompose(exH, sExclH[w]);

    // ---- correction: y = y0 + u*s1 + v*s2 (chain-free) ----
    if (valid) {
        float2 sL = resetCk ? make_float2(0.f, 0.f) : mapApply(exL, vin.x, vin.y);
        float2 sH = resetCk ? make_float2(0.f, 0.f) : mapApply(exH, vin.z, vin.w);
        float sL1 = sL.x, sL2 = sL.y, nsH1 = -sH.x, nsH2 = -sH.y;
        float* cb = sbuf + t * CHUNK;
#pragma unroll 1
        for (int k = 0; k < CHUNK; k += 4) {
            float4 yv = *reinterpret_cast<const float4*>(cb + k);
            float4 t0 = stab[k], t1 = stab[k + 1], t2 = stab[k + 2], t3 = stab[k + 3];
            yv.x += fmaf(t0.x, sL1, fmaf(t0.y, sL2, fmaf(t0.z, nsH1, t0.w * nsH2)));
            yv.y += fmaf(t1.x, sL1, fmaf(t1.y, sL2, fmaf(t1.z, nsH1, t1.w * nsH2)));
            yv.z += fmaf(t2.x, sL1, fmaf(t2.y, sL2, fmaf(t2.z, nsH1, t2.w * nsH2)));
            yv.w += fmaf(t3.x, sL1, fmaf(t3.y, sL2, fmaf(t3.z, nsH1, t3.w * nsH2)));
            *reinterpret_cast<float4*>(cb + k) = yv;
        }
    }
    __syncthreads();

    // ---- coalesced store ----
    float4* og4 = (float4*)out;
#pragma unroll
    for (int i = 0; i < F4PB / BT; i++) {
        size_t idx = base4 + t + (size_t)i * BT;
        if (idx < TOTAL_F4) og4[idx] = s4[t + i * BT];
    }
}

extern "C" void kernel_launch(void* const* d_in, const int* in_sizes, int n_in,
                              void* d_out, int out_size) {
    const float* audio = (const float*)d_in[0];
    const int*   sr    = (const int*)d_in[1];
    const float* cl    = (const float*)d_in[2];
    const float* ch    = (const float*)d_in[3];
    float* out = (float*)d_out;

    init_kernel<<<(NBLK + 255) / 256, 256>>>();
    fused_kernel<<<NBLK, BT>>>(audio, out, sr, cl, ch);
}